// round 15
// baseline (speedup 1.0000x reference)
#include <cuda_runtime.h>
#include <cstdint>

// NonLocalMeansSmoothing: x [8,256,256,8] fp32 -> same. K=5, sigma=1, h=1.
// w ∝ exp(-(||c-n||^2 + 0.5*(di^2+dj^2)))  (gaussian global norm cancels)
//
// R15: R14's body verbatim (1 px/thread, direct packed-difference distance,
// 2 LDS.128/tap, 42-reg cap, 48 warps/SM) but with 256-thread CTAs
// (32x8 tile, 6 CTAs/SM instead of 3x512): halves each barrier/halo phase
// shadow and doubles the co-resident CTAs covering it; finer tile
// quantization across SMs (2048 CTAs).

#define BATCH 8
#define NX 256
#define NY 256
#define TILEX 32            // columns (ny)
#define TILEY 8             // rows (nx)
#define HALO 2
#define SMX (TILEX + 2 * HALO)   // 36
#define SMY (TILEY + 2 * HALO)   // 12
#define L2E 1.4426950408889634f

typedef unsigned long long u64;

__device__ __forceinline__ u64 fma2(u64 a, u64 b, u64 c) {
    u64 d; asm("fma.rn.f32x2 %0,%1,%2,%3;" : "=l"(d) : "l"(a), "l"(b), "l"(c)); return d;
}
__device__ __forceinline__ u64 mul2(u64 a, u64 b) {
    u64 d; asm("mul.rn.f32x2 %0,%1,%2;" : "=l"(d) : "l"(a), "l"(b)); return d;
}
__device__ __forceinline__ u64 sub2(u64 a, u64 b) {
    u64 d; asm("sub.rn.f32x2 %0,%1,%2;" : "=l"(d) : "l"(a), "l"(b)); return d;
}
__device__ __forceinline__ u64 add2(u64 a, u64 b) {
    u64 d; asm("add.rn.f32x2 %0,%1,%2;" : "=l"(d) : "l"(a), "l"(b)); return d;
}
__device__ __forceinline__ u64 pack2(float lo, float hi) {
    u64 d; asm("mov.b64 %0,{%1,%2};" : "=l"(d) : "f"(lo), "f"(hi)); return d;
}
__device__ __forceinline__ float hadd2(u64 a) {
    float lo, hi; asm("mov.b64 {%0,%1},%2;" : "=f"(lo), "=f"(hi) : "l"(a));
    return lo + hi;
}
__device__ __forceinline__ float ex2f(float x) {
    float r; asm("ex2.approx.ftz.f32 %0,%1;" : "=f"(r) : "f"(x)); return r;
}
__device__ __forceinline__ int refl(int p, int n) {
    if (p < 0) p = -p;
    if (p >= n) p = 2 * n - 2 - p;
    return p;
}

__global__ __launch_bounds__(256, 6)
void nlm_kernel(const float* __restrict__ x, float* __restrict__ out) {
    __shared__ ulonglong2 sm0[SMY][SMX];   // ch 0-3
    __shared__ ulonglong2 sm1[SMY][SMX];   // ch 4-7

    const int b   = blockIdx.z;
    const int ti0 = blockIdx.y * TILEY;
    const int tj0 = blockIdx.x * TILEX;
    const int tid = threadIdx.y * 32 + threadIdx.x;

    const float* xb = x + (size_t)b * NX * NY * 8;

    // Halo load: 432 sites / 256 threads.
    for (int p = tid; p < SMY * SMX; p += 256) {
        int r = p / SMX;
        int c = p - r * SMX;
        int gi = refl(ti0 + r - HALO, NX);
        int gj = refl(tj0 + c - HALO, NY);
        const float4* src = reinterpret_cast<const float4*>(
            xb + ((size_t)gi * NY + gj) * 8);
        *reinterpret_cast<float4*>(&sm0[r][c]) = src[0];
        *reinterpret_cast<float4*>(&sm1[r][c]) = src[1];
    }
    __syncthreads();

    const int li = threadIdx.y + HALO;
    const int lj = threadIdx.x + HALO;

    const ulonglong2 C0 = sm0[li][lj];
    const ulonglong2 C1 = sm1[li][lj];

    u64 a0 = 0, a1 = 0, a2 = 0, a3 = 0;
    float wsum = 0.f;

#pragma unroll
    for (int di = -HALO; di <= HALO; di++) {
#pragma unroll
        for (int dj = -HALO; dj <= HALO; dj++) {
            const ulonglong2 N0 = sm0[li + di][lj + dj];
            const ulonglong2 N1 = sm1[li + di][lj + dj];

            // ||c-n||^2 via packed differences, tree-shaped.
            u64 t0 = sub2(C0.x, N0.x);
            u64 t1 = sub2(C0.y, N0.y);
            u64 t2 = sub2(C1.x, N1.x);
            u64 t3 = sub2(C1.y, N1.y);
            u64 d1 = mul2(t0, t0);
            u64 d2 = mul2(t1, t1);
            d1 = fma2(t2, t2, d1);
            d2 = fma2(t3, t3, d2);
            const float d = hadd2(add2(d1, d2));

            const float cg = -L2E * (0.5f * (float)(di * di + dj * dj));
            const float w = ex2f(fmaf(-L2E, d, cg));
            const u64 w2 = pack2(w, w);
            a0 = fma2(w2, N0.x, a0);
            a1 = fma2(w2, N0.y, a1);
            a2 = fma2(w2, N1.x, a2);
            a3 = fma2(w2, N1.y, a3);
            wsum += w;
        }
    }

    const float inv = __fdividef(1.f, wsum);
    const u64 inv2 = pack2(inv, inv);
    ulonglong2 r0, r1;
    r0.x = mul2(a0, inv2); r0.y = mul2(a1, inv2);
    r1.x = mul2(a2, inv2); r1.y = mul2(a3, inv2);

    const int gi = ti0 + threadIdx.y;
    const int gj = tj0 + threadIdx.x;
    ulonglong2* dst = reinterpret_cast<ulonglong2*>(
        out + (((size_t)b * NX + gi) * NY + gj) * 8);
    dst[0] = r0;
    dst[1] = r1;
}

extern "C" void kernel_launch(void* const* d_in, const int* in_sizes, int n_in,
                              void* d_out, int out_size) {
    const float* x = (const float*)d_in[0];
    float* out = (float*)d_out;
    dim3 block(32, 8, 1);
    dim3 grid(NY / TILEX, NX / TILEY, BATCH);  // (8, 32, 8) = 2048 CTAs
    nlm_kernel<<<grid, block>>>(x, out);
}